// round 1
// baseline (speedup 1.0000x reference)
#include <cuda_runtime.h>
#include <cstdint>

#define NUM_ANCHORS 145152
#define NUM_CH 85
#define IMG_SIZE 1536.0f

// d_out layout (fp32), matching the reference tuple order, flattened:
//   [0 .. 4N)        bboxes   (N,4)  = x, y, X, Y
//   [4N .. 5N)       scores   (N,)   = objectness * class_conf
//   [5N .. 6N)       class_pred (N,) = argmax class index (as float)
//   [6N .. 12N)      detections (N,6) = x, y, X, Y, class_conf, class_pred
__global__ __launch_bounds__(256)
void yolo_decode_kernel(const float* __restrict__ pred,
                        float* __restrict__ out)
{
    const unsigned FULL = 0xffffffffu;
    int gwarp = (blockIdx.x * blockDim.x + threadIdx.x) >> 5;
    int lane  = threadIdx.x & 31;
    if (gwarp >= NUM_ANCHORS) return;

    const float* row = pred + (long long)gwarp * NUM_CH;

    // Coalesced row load: 340 contiguous bytes per warp.
    float p0 = row[lane];            // channels   0..31
    float p1 = row[lane + 32];       // channels  32..63
    float p2 = (lane < NUM_CH - 64) ? row[lane + 64] : -1e30f;  // 64..84

    // --- per-lane best class (channels 5..84), lowest-index tie-break ---
    // Candidates within a lane appear in increasing channel order, so a
    // strict > keeps the lowest index on exact ties.
    float bv = -1e30f;
    int   bi = 0x7fffffff;
    if (lane >= 5)                 { bv = p0; bi = lane; }
    if (p1 > bv)                   { bv = p1; bi = lane + 32; }
    if (lane < NUM_CH - 64 && p2 > bv) { bv = p2; bi = lane + 64; }

    // --- warp butterfly max+argmax, lowest index wins ties ---
    #pragma unroll
    for (int off = 16; off > 0; off >>= 1) {
        float ov = __shfl_xor_sync(FULL, bv, off);
        int   oi = __shfl_xor_sync(FULL, bi, off);
        if (ov > bv || (ov == bv && oi < bi)) { bv = ov; bi = oi; }
    }

    // --- broadcast header channels (cx, cy, w, h, objectness) ---
    float cx  = __shfl_sync(FULL, p0, 0);
    float cy  = __shfl_sync(FULL, p0, 1);
    float w   = __shfl_sync(FULL, p0, 2);
    float h   = __shfl_sync(FULL, p0, 3);
    float obj = __shfl_sync(FULL, p0, 4);

    // Match reference op order: divide by IMG_SIZE first, then +/- half.
    float bx = cx / IMG_SIZE;
    float by = cy / IMG_SIZE;
    float bw = w  / IMG_SIZE;
    float bh = h  / IMG_SIZE;
    float x0 = bx - bw * 0.5f;
    float y0 = by - bh * 0.5f;
    float x1 = bx + bw * 0.5f;
    float y1 = by + bh * 0.5f;

    float conf  = bv;
    float clsf  = (float)(bi - 5);
    float score = obj * conf;

    float* out_bb  = out;
    float* out_sc  = out + (long long)NUM_ANCHORS * 4;
    float* out_cls = out + (long long)NUM_ANCHORS * 5;
    float* out_det = out + (long long)NUM_ANCHORS * 6;

    // Distributed writes: lanes 0-3 bbox, 4 score, 5 class, 8-13 detections.
    if (lane < 4) {
        float v = (lane == 0) ? x0 : (lane == 1) ? y0 : (lane == 2) ? x1 : y1;
        out_bb[(long long)gwarp * 4 + lane] = v;
    } else if (lane == 4) {
        out_sc[gwarp] = score;
    } else if (lane == 5) {
        out_cls[gwarp] = clsf;
    }
    if (lane >= 8 && lane < 14) {
        int c = lane - 8;
        float v = (c == 0) ? x0 : (c == 1) ? y0 : (c == 2) ? x1 :
                  (c == 3) ? y1 : (c == 4) ? conf : clsf;
        out_det[(long long)gwarp * 6 + c] = v;
    }
}

extern "C" void kernel_launch(void* const* d_in, const int* in_sizes, int n_in,
                              void* d_out, int out_size)
{
    const float* pred = (const float*)d_in[0];
    // d_in[1] = score_threshold — unused by the reference computation.
    float* out = (float*)d_out;

    const int warps_per_block = 8;           // 256 threads
    const int total_warps     = NUM_ANCHORS; // one warp per anchor
    int blocks = (total_warps + warps_per_block - 1) / warps_per_block;
    yolo_decode_kernel<<<blocks, warps_per_block * 32>>>(pred, out);
}

// round 2
// speedup vs baseline: 2.4450x; 2.4450x over previous
#include <cuda_runtime.h>
#include <cstdint>

#define NUM_ANCHORS 145152
#define NUM_CH 85
#define IMG_SIZE 1536.0f
#define ROWS_PER_BLOCK 128
#define THREADS 128

// d_out layout (fp32), matching the reference tuple order, flattened:
//   [0 .. 4N)    bboxes     (N,4) = x0, y0, x1, y1
//   [4N .. 5N)   scores     (N,)
//   [5N .. 6N)   class_pred (N,)  (as float)
//   [6N .. 12N)  detections (N,6) = x0, y0, x1, y1, conf, cls
__global__ __launch_bounds__(THREADS)
void yolo_decode_kernel(const float* __restrict__ pred,
                        float* __restrict__ out)
{
    __shared__ float tile[ROWS_PER_BLOCK * NUM_CH];  // 43520 B

    const int tid  = threadIdx.x;
    const int row0 = blockIdx.x * ROWS_PER_BLOCK;    // grid divides exactly

    // ---- Stage 128 contiguous rows into smem with coalesced float4 loads ----
    // Tile is 128*85 = 10880 floats = 2720 float4; block base is 16B-aligned
    // because ROWS_PER_BLOCK*NUM_CH*4 = 43520 is a multiple of 16.
    {
        const float4* src = (const float4*)(pred + (long long)row0 * NUM_CH);
        float4* dst = (float4*)tile;
        const int n4 = ROWS_PER_BLOCK * NUM_CH / 4;  // 2720
        #pragma unroll 4
        for (int j = tid; j < n4; j += THREADS)
            dst[j] = src[j];
    }
    __syncthreads();

    // ---- One thread per anchor; smem row stride 85 (odd) => conflict-free ----
    const float* s = tile + tid * NUM_CH;
    const int anchor = row0 + tid;

    float cx  = s[0];
    float cy  = s[1];
    float w   = s[2];
    float h   = s[3];
    float obj = s[4];

    // argmax over classes 5..84, lowest index wins ties (strict >)
    float best = s[5];
    int   bi   = 0;
    #pragma unroll
    for (int c = 6; c < NUM_CH; ++c) {
        float v = s[c];
        if (v > best) { best = v; bi = c - 5; }
    }

    // Match reference op order: /IMG_SIZE first, then +/- half.
    float bx = cx / IMG_SIZE;
    float by = cy / IMG_SIZE;
    float bw = w  / IMG_SIZE;
    float bh = h  / IMG_SIZE;
    float x0 = bx - bw * 0.5f;
    float y0 = by - bh * 0.5f;
    float x1 = bx + bw * 0.5f;
    float y1 = by + bh * 0.5f;

    float conf  = best;
    float clsf  = (float)bi;
    float score = obj * conf;

    float* out_sc  = out + (long long)NUM_ANCHORS * 4;
    float* out_cls = out + (long long)NUM_ANCHORS * 5;
    float* out_det = out + (long long)NUM_ANCHORS * 6;

    // Vectorized, coalesced stores.
    ((float4*)out)[anchor] = make_float4(x0, y0, x1, y1);
    out_sc[anchor]  = score;
    out_cls[anchor] = clsf;

    float2* det = (float2*)(out_det + (long long)anchor * 6);
    det[0] = make_float2(x0, y0);
    det[1] = make_float2(x1, y1);
    det[2] = make_float2(conf, clsf);
}

extern "C" void kernel_launch(void* const* d_in, const int* in_sizes, int n_in,
                              void* d_out, int out_size)
{
    const float* pred = (const float*)d_in[0];
    // d_in[1] = score_threshold — unused by the reference computation.
    float* out = (float*)d_out;

    int blocks = NUM_ANCHORS / ROWS_PER_BLOCK;  // 145152/128 = 1134 exactly
    yolo_decode_kernel<<<blocks, THREADS>>>(pred, out);
}